// round 13
// baseline (speedup 1.0000x reference)
#include <cuda_runtime.h>
#include <cuda_fp16.h>
#include <cstdint>

// Problem constants (fixed by the reference)
#define NN 50000
#define NE 600000
#define NG 64
#define D_IN 128
#define D_HID 128
#define D_OUT 64

// ---------------- device scratch (no allocs allowed) ----------------
// Invariant: g_cnt, g_gsum, g_gcnt are ZERO at entry of every kernel_launch
// call (BSS-zero initially; re-zeroed at the end of k_fill / k_final).
__device__ __align__(16) int    g_cnt[NN];        // in-degree (edges only)
__device__ __align__(16) float  g_dinv[NN];
__device__ __align__(16) int    g_rowptr[NN + 1];
__device__ __align__(16) int    g_fillptr[NN];
__device__ __align__(16) int    g_bsum[256];
__device__ __align__(16) int    g_col[NE];
__device__ __align__(16) __half g_w2h[D_HID * D_OUT];  // fp16 W2
__device__ __align__(16) __half g_hs1[NN * D_HID];   // (x@W1)*dinv[row], fp16
__device__ __align__(16) __half g_out1[NN * D_HID];  // relu(layer1 agg), fp16
__device__ __align__(16) __half g_hs2[NN * D_OUT];   // (out1@W2)*dinv[row], fp16
__device__ __align__(16) float  g_gsum[NG * D_OUT];
__device__ __align__(16) int    g_gcnt[NG];

// ------- degree (4 edges/thread) + graph histogram + W2 fp16 convert -------
__global__ void k_deg(const int* __restrict__ ei, const int* __restrict__ batch,
                      const float* __restrict__ W2, int e4, int n) {
    __shared__ int hist[NG];
    int t = threadIdx.x;
    if (t < NG) hist[t] = 0;
    __syncthreads();
    int i = blockIdx.x * blockDim.x + t;
    if (i < e4) {                         // 4 dst indices, one 16B load
        int4 d = ((const int4*)ei)[e4 + i];
        atomicAdd(&g_cnt[d.x], 1);
        atomicAdd(&g_cnt[d.y], 1);
        atomicAdd(&g_cnt[d.z], 1);
        atomicAdd(&g_cnt[d.w], 1);
    }
    if (i < n) atomicAdd(&hist[batch[i]], 1);
    if (i < (D_HID * D_OUT) / 2) {
        float2 v = ((const float2*)W2)[i];
        ((__half2*)g_w2h)[i] = __floats2half2_rn(v.x, v.y);
    }
    __syncthreads();
    if (t < NG && hist[t]) atomicAdd(&g_gcnt[t], hist[t]);
}

// ---------------- CSR scan pass 1 + dinv ----------------
// dinv depends only on g_cnt (final after k_deg), so computing it here lets
// mma1 (which needs dinv in its epilogue) fork right after this kernel and
// overlap scan3 + fill.
__global__ void k_scan1(int n) {
    __shared__ int s[256];
    int t = threadIdx.x, b = blockIdx.x;
    int i = b * 256 + t;
    int v = (i < n) ? g_cnt[i] : 0;
    if (i < n) g_dinv[i] = rsqrtf((float)(v + 1));   // self-loop folded
    s[t] = v;
    __syncthreads();
    #pragma unroll
    for (int off = 1; off < 256; off <<= 1) {
        int add = (t >= off) ? s[t - off] : 0;
        __syncthreads();
        s[t] += add;
        __syncthreads();
    }
    if (i < n) g_rowptr[i] = s[t] - v;       // block-local exclusive
    if (t == 255) g_bsum[b] = s[255];
}

// finalize: every block redundantly scans the 196 block sums in smem,
// applies its offset.
__global__ void k_scan3(int n, int e, int nb) {
    __shared__ int s[256];
    int t = threadIdx.x, b = blockIdx.x;
    int v = (t < nb) ? g_bsum[t] : 0;
    s[t] = v;
    __syncthreads();
    #pragma unroll
    for (int off = 1; off < 256; off <<= 1) {
        int add = (t >= off) ? s[t - off] : 0;
        __syncthreads();
        s[t] += add;
        __syncthreads();
    }
    int boff = (b == 0) ? 0 : s[b - 1];

    int i = b * 256 + t;
    if (i < n) {
        int val = g_rowptr[i] + boff;
        g_rowptr[i] = val;
        g_fillptr[i] = val;
    }
    if (i == 0) g_rowptr[n] = e;
}

// fill CSR cols (4 edges/thread); re-zero g_cnt for the next replay
__global__ void k_fill(const int* __restrict__ ei, int e4, int n) {
    int i = blockIdx.x * blockDim.x + threadIdx.x;
    if (i < e4) {
        int4 s = ((const int4*)ei)[i];
        int4 d = ((const int4*)ei)[e4 + i];
        int p0 = atomicAdd(&g_fillptr[d.x], 1);
        int p1 = atomicAdd(&g_fillptr[d.y], 1);
        int p2 = atomicAdd(&g_fillptr[d.z], 1);
        int p3 = atomicAdd(&g_fillptr[d.w], 1);
        g_col[p0] = s.x;
        g_col[p1] = s.y;
        g_col[p2] = s.z;
        g_col[p3] = s.w;
    }
    if (i < n) g_cnt[i] = 0;
}

// ---------------- tensor-core GEMM ----------------
// out[r,:] = half( (X[r,:128] @ W[:128,:N]) * dinv[r] )
// LAYER=1: X = fp32 arg, W = fp32 arg (converted in-kernel) -> g_hs1.
// LAYER=2: X = g_out1 (fp16), W = g_w2h -> g_hs2.
__device__ __forceinline__ uint32_t smem_u32(const void* p) {
    return (uint32_t)__cvta_generic_to_shared(p);
}
__device__ __forceinline__ void ldsm_x4(uint32_t& a0, uint32_t& a1,
                                        uint32_t& a2, uint32_t& a3, uint32_t addr) {
    asm volatile("ldmatrix.sync.aligned.m8n8.x4.shared.b16 {%0,%1,%2,%3},[%4];"
                 : "=r"(a0), "=r"(a1), "=r"(a2), "=r"(a3) : "r"(addr));
}
__device__ __forceinline__ void ldsm_x2t(uint32_t& b0, uint32_t& b1, uint32_t addr) {
    asm volatile("ldmatrix.sync.aligned.m8n8.x2.trans.shared.b16 {%0,%1},[%2];"
                 : "=r"(b0), "=r"(b1) : "r"(addr));
}
__device__ __forceinline__ void mma16816(float* c, uint32_t a0, uint32_t a1,
                                         uint32_t a2, uint32_t a3,
                                         uint32_t b0, uint32_t b1) {
    asm volatile(
        "mma.sync.aligned.m16n8k16.row.col.f32.f16.f16.f32 "
        "{%0,%1,%2,%3}, {%4,%5,%6,%7}, {%8,%9}, {%0,%1,%2,%3};"
        : "+f"(c[0]), "+f"(c[1]), "+f"(c[2]), "+f"(c[3])
        : "r"(a0), "r"(a1), "r"(a2), "r"(a3), "r"(b0), "r"(b1));
}
__device__ __forceinline__ uint4 f8_to_h8(float4 f0, float4 f1) {
    __half2 p0 = __floats2half2_rn(f0.x, f0.y), p1 = __floats2half2_rn(f0.z, f0.w);
    __half2 p2 = __floats2half2_rn(f1.x, f1.y), p3 = __floats2half2_rn(f1.z, f1.w);
    uint4 v;
    v.x = *(uint32_t*)&p0; v.y = *(uint32_t*)&p1;
    v.z = *(uint32_t*)&p2; v.w = *(uint32_t*)&p3;
    return v;
}

template <int N, int LAYER>
__global__ __launch_bounds__(256) void k_mma(const float* __restrict__ Xf,
                                             const float* __restrict__ Wf, int M) {
    constexpr int K  = 128;
    constexpr int UW = N / 8;            // 16B units per W row
    constexpr int NJ = N / 32;           // 8-col n-tiles per warp
    __shared__ __align__(16) __half Xs[64 * K];
    __shared__ __align__(16) __half Ws[K * N];

    int tid = threadIdx.x;
    int row0 = blockIdx.x * 64;

    // ---- load W (swizzled) ----
    if (LAYER == 1) {
        // fp32 source, convert in-kernel (keeps mma1 independent of k_deg)
        #pragma unroll
        for (int t = tid; t < K * UW; t += 256) {
            int r = t / UW, u = t % UW;
            const float4* src = (const float4*)(Wf + r * N + u * 8);
            uint4 v = f8_to_h8(src[0], src[1]);
            *(uint4*)(Ws + ((r * UW) + (u ^ (r & 7))) * 8) = v;
        }
    } else {
        const uint4* Wh = (const uint4*)g_w2h;
        #pragma unroll
        for (int t = tid; t < K * UW; t += 256) {
            int r = t / UW, u = t % UW;
            *(uint4*)(Ws + ((r * UW) + (u ^ (r & 7))) * 8) = Wh[r * UW + u];
        }
    }
    // ---- load X tile (swizzled) ----
    if (LAYER == 1) {
        #pragma unroll
        for (int t = tid; t < 64 * 16; t += 256) {
            int r = t / 16, u = t % 16;
            int gr = min(row0 + r, M - 1);
            const float4* src = (const float4*)(Xf + (size_t)gr * K + u * 8);
            uint4 v = f8_to_h8(src[0], src[1]);
            *(uint4*)(Xs + ((r * 16) + (u ^ (r & 7))) * 8) = v;
        }
    } else {
        const uint4* Xh = (const uint4*)g_out1;
        #pragma unroll
        for (int t = tid; t < 64 * 16; t += 256) {
            int r = t / 16, u = t % 16;
            int gr = min(row0 + r, M - 1);
            uint4 v = Xh[(size_t)gr * 16 + u];
            *(uint4*)(Xs + ((r * 16) + (u ^ (r & 7))) * 8) = v;
        }
    }
    __syncthreads();

    int lane = tid & 31, wid = tid >> 5;
    int wm = wid >> 2;                   // 0..1  (32-row group)
    int wn = wid & 3;                    // 0..3  (N/4-col group)

    float acc[2][NJ][4];
    #pragma unroll
    for (int mt = 0; mt < 2; mt++)
        #pragma unroll
        for (int j = 0; j < NJ; j++)
            #pragma unroll
            for (int q = 0; q < 4; q++) acc[mt][j][q] = 0.0f;

    int asel = lane >> 4;
    int brr = lane & 15;

    #pragma unroll
    for (int ks = 0; ks < 8; ks++) {
        uint32_t a[2][4];
        int uA = ks * 2 + asel;
        #pragma unroll
        for (int mt = 0; mt < 2; mt++) {
            int ar = wm * 32 + mt * 16 + (lane & 15);
            ldsm_x4(a[mt][0], a[mt][1], a[mt][2], a[mt][3],
                    smem_u32(&Xs[((ar * 16) + (uA ^ (ar & 7))) * 8]));
        }
        int rB = ks * 16 + brr;
        #pragma unroll
        for (int j = 0; j < NJ; j++) {
            int uB = wn * (N / 32) + j;
            uint32_t b0, b1;
            ldsm_x2t(b0, b1, smem_u32(&Ws[((rB * UW) + (uB ^ (rB & 7))) * 8]));
            #pragma unroll
            for (int mt = 0; mt < 2; mt++)
                mma16816(acc[mt][j], a[mt][0], a[mt][1], a[mt][2], a[mt][3], b0, b1);
        }
    }

    // ---- epilogue: *dinv, fp16 store ----
    __half2* out = (LAYER == 1) ? (__half2*)g_hs1 : (__half2*)g_hs2;
    #pragma unroll
    for (int mt = 0; mt < 2; mt++) {
        int gr0 = row0 + wm * 32 + mt * 16 + (lane >> 2);
        int gr1 = gr0 + 8;
        float dv0 = (gr0 < M) ? g_dinv[gr0] : 0.0f;
        float dv1 = (gr1 < M) ? g_dinv[gr1] : 0.0f;
        #pragma unroll
        for (int j = 0; j < NJ; j++) {
            int c2 = wn * (N / 8) + j * 4 + (lane & 3);
            if (gr0 < M)
                out[(size_t)gr0 * (N / 2) + c2] =
                    __floats2half2_rn(acc[mt][j][0] * dv0, acc[mt][j][1] * dv0);
            if (gr1 < M)
                out[(size_t)gr1 * (N / 2) + c2] =
                    __floats2half2_rn(acc[mt][j][2] * dv1, acc[mt][j][3] * dv1);
        }
    }
}

__device__ __forceinline__ void acc_u2(float2& a0, float2& a1, uint2 v) {
    float2 f0 = __half22float2(*(__half2*)&v.x);
    float2 f1 = __half22float2(*(__half2*)&v.y);
    a0.x += f0.x; a0.y += f0.y;
    a1.x += f1.x; a1.y += f1.y;
}

// ---------------- aggregation layer 1 (DIM=128, fp16 in/out) ----------
// One uint2 (8B) load per lane per neighbor row: lane covers cols 4l..4l+3.
__global__ __launch_bounds__(256) void k_agg1(const float* __restrict__ bias, int n) {
    const uint2* hs = (const uint2*)g_hs1;   // row = 32 uint2
    int warp = (blockIdx.x * blockDim.x + threadIdx.x) >> 5;
    int lane = threadIdx.x & 31;
    if (warp >= n) return;
    int node = warp;

    float2 a0 = {0.f, 0.f}, a1 = {0.f, 0.f};
    acc_u2(a0, a1, hs[(size_t)node * 32 + lane]);   // self

    int e = g_rowptr[node];
    int t = g_rowptr[node + 1];
    for (; e + 4 <= t; e += 4) {
        int c0 = g_col[e], c1 = g_col[e + 1], c2 = g_col[e + 2], c3 = g_col[e + 3];
        uint2 v0 = hs[(size_t)c0 * 32 + lane];
        uint2 v1 = hs[(size_t)c1 * 32 + lane];
        uint2 v2 = hs[(size_t)c2 * 32 + lane];
        uint2 v3 = hs[(size_t)c3 * 32 + lane];
        acc_u2(a0, a1, v0); acc_u2(a0, a1, v1);
        acc_u2(a0, a1, v2); acc_u2(a0, a1, v3);
    }
    for (; e < t; e++)
        acc_u2(a0, a1, hs[(size_t)g_col[e] * 32 + lane]);

    float dv = g_dinv[node];
    float4 bb = ((const float4*)bias)[lane];   // cols 4l..4l+3
    __half2 o0 = __floats2half2_rn(fmaxf(fmaf(a0.x, dv, bb.x), 0.0f),
                                   fmaxf(fmaf(a0.y, dv, bb.y), 0.0f));
    __half2 o1 = __floats2half2_rn(fmaxf(fmaf(a1.x, dv, bb.z), 0.0f),
                                   fmaxf(fmaf(a1.y, dv, bb.w), 0.0f));
    uint2 st;
    st.x = *(uint32_t*)&o0; st.y = *(uint32_t*)&o1;
    ((uint2*)g_out1)[(size_t)node * 32 + lane] = st;
}

__device__ __forceinline__ void acc_h2(float2& a, __half2 h) {
    float2 f = __half22float2(h);
    a.x += f.x; a.y += f.y;
}

// ---------------- aggregation layer 2 (DIM=64, fp16 in, pool) ----------
__global__ __launch_bounds__(256) void k_agg2(const float* __restrict__ bias,
                                              const int* __restrict__ batch, int n) {
    const __half2* hs = (const __half2*)g_hs2;   // row = 32 half2
    int warp = (blockIdx.x * blockDim.x + threadIdx.x) >> 5;
    int lane = threadIdx.x & 31;
    if (warp >= n) return;
    int node = warp;

    float2 a0 = __half22float2(hs[(size_t)node * 32 + lane]);

    int e = g_rowptr[node];
    int t = g_rowptr[node + 1];
    for (; e + 4 <= t; e += 4) {
        int c0 = g_col[e], c1 = g_col[e + 1], c2 = g_col[e + 2], c3 = g_col[e + 3];
        __half2 v0 = hs[(size_t)c0 * 32 + lane];
        __half2 v1 = hs[(size_t)c1 * 32 + lane];
        __half2 v2 = hs[(size_t)c2 * 32 + lane];
        __half2 v3 = hs[(size_t)c3 * 32 + lane];
        acc_h2(a0, v0); acc_h2(a0, v1); acc_h2(a0, v2); acc_h2(a0, v3);
    }
    for (; e < t; e++)
        acc_h2(a0, hs[(size_t)g_col[e] * 32 + lane]);

    float dv = g_dinv[node];
    float2 bb = ((const float2*)bias)[lane];
    int gidx = batch[node];
    atomicAdd(&g_gsum[gidx * D_OUT + 2 * lane + 0], fmaf(a0.x, dv, bb.x));
    atomicAdd(&g_gsum[gidx * D_OUT + 2 * lane + 1], fmaf(a0.y, dv, bb.y));
}

// ---------------- final divide + re-zero pool state ----------------
__global__ void k_final(float* __restrict__ out) {
    int i = blockIdx.x * blockDim.x + threadIdx.x;
    if (i < NG * D_OUT) {
        int g = i / D_OUT;
        float c = (float)max(g_gcnt[g], 1);
        out[i] = g_gsum[i] / c;
        g_gsum[i] = 0.0f;
    }
    if (i < NG) g_gcnt[i] = 0;
}

// ---------------- launch (graph-capturable; fork after scan1) ----------
extern "C" void kernel_launch(void* const* d_in, const int* in_sizes, int n_in,
                              void* d_out, int out_size) {
    const float* x = nullptr; const int* ei = nullptr; const int* batch = nullptr;
    const float* W1 = nullptr; const float* b1 = nullptr;
    const float* W2 = nullptr; const float* b2 = nullptr;
    for (int i = 0; i < n_in; i++) {
        switch (in_sizes[i]) {
            case NN * D_IN:      x     = (const float*)d_in[i]; break;
            case 2 * NE:         ei    = (const int*)d_in[i];   break;
            case NN:             batch = (const int*)d_in[i];   break;
            case D_IN * D_HID:   W1    = (const float*)d_in[i]; break;
            case D_HID * D_OUT:  W2    = (const float*)d_in[i]; break;
            case D_HID:          b1    = (const float*)d_in[i]; break;
            case D_OUT:          b2    = (const float*)d_in[i]; break;
        }
    }
    float* out = (float*)d_out;

    const int n = NN, e = NE;
    const int e4 = NE / 4;                // 150000
    const int nb256n = (n + 255) / 256;   // 196
    const int nb256e4 = (e4 + 255) / 256; // 586
    int gb = (n + 63) / 64;               // 782

    // Main: degree then scan1 (which also produces dinv).
    k_deg<<<nb256e4, 256>>>(ei, batch, W2, e4, n);
    k_scan1<<<nb256n, 256>>>(n);

    // Fork after scan1: mma1 (needs only x, W1, dinv) overlaps scan3 + fill.
    cudaStream_t side;
    cudaEvent_t evFork, evJoin;
    cudaStreamCreateWithFlags(&side, cudaStreamNonBlocking);
    cudaEventCreateWithFlags(&evFork, cudaEventDisableTiming);
    cudaEventCreateWithFlags(&evJoin, cudaEventDisableTiming);

    cudaEventRecord(evFork, 0);
    cudaStreamWaitEvent(side, evFork, 0);
    k_mma<128, 1><<<gb, 256, 0, side>>>(x, W1, n);
    cudaEventRecord(evJoin, side);

    // Main branch continues the CSR build.
    k_scan3<<<nb256n, 256>>>(n, e, nb256n);
    k_fill<<<nb256e4, 256>>>(ei, e4, n);

    // Join: agg1 needs both the CSR and hs1.
    cudaStreamWaitEvent(0, evJoin, 0);
    k_agg1<<<(n + 7) / 8, 256>>>(b1, n);
    k_mma<64, 2><<<gb, 256>>>(nullptr, nullptr, n);
    k_agg2<<<(n + 7) / 8, 256>>>(b2, batch, n);
    k_final<<<(NG * D_OUT + 255) / 256, 256>>>(out);
}

// round 15
// speedup vs baseline: 1.0056x; 1.0056x over previous
#include <cuda_runtime.h>
#include <cuda_fp16.h>
#include <cstdint>

// Problem constants (fixed by the reference)
#define NN 50000
#define NE 600000
#define NG 64
#define D_IN 128
#define D_HID 128
#define D_OUT 64

// ---------------- device scratch (no allocs allowed) ----------------
// Invariant: g_cnt, g_gsum, g_gcnt are ZERO at entry of every kernel_launch
// call (BSS-zero initially; re-zeroed at the end of k_fill / k_final).
__device__ __align__(16) int    g_cnt[NN];        // in-degree (edges only)
__device__ __align__(16) float  g_dinv[NN];
__device__ __align__(16) int    g_rowptr[NN + 1];
__device__ __align__(16) int    g_rank[NE];       // per-edge insertion rank
__device__ __align__(16) int    g_bsum[256];
__device__ __align__(16) int    g_col[NE];
__device__ __align__(16) __half g_w2h[D_HID * D_OUT];  // fp16 W2
__device__ __align__(16) __half g_hs1[NN * D_HID];   // (x@W1)*dinv[row], fp16
__device__ __align__(16) __half g_out1[NN * D_HID];  // relu(layer1 agg), fp16
__device__ __align__(16) __half g_hs2[NN * D_OUT];   // (out1@W2)*dinv[row], fp16
__device__ __align__(16) float  g_gsum[NG * D_OUT];
__device__ __align__(16) int    g_gcnt[NG];

// ------- degree + per-edge rank + graph histogram + W2 fp16 convert -------
// The atomicAdd return value IS the edge's insertion slot within its dst
// row — persisting it makes the later CSR fill atomic-free.
__global__ void k_deg(const int* __restrict__ ei, const int* __restrict__ batch,
                      const float* __restrict__ W2, int e4, int n) {
    __shared__ int hist[NG];
    int t = threadIdx.x;
    if (t < NG) hist[t] = 0;
    __syncthreads();
    int i = blockIdx.x * blockDim.x + t;
    if (i < e4) {                         // 4 dst indices, one 16B load
        int4 d = ((const int4*)ei)[e4 + i];
        int4 r;
        r.x = atomicAdd(&g_cnt[d.x], 1);
        r.y = atomicAdd(&g_cnt[d.y], 1);
        r.z = atomicAdd(&g_cnt[d.z], 1);
        r.w = atomicAdd(&g_cnt[d.w], 1);
        ((int4*)g_rank)[i] = r;           // streaming 16B store
    }
    if (i < n) atomicAdd(&hist[batch[i]], 1);
    if (i < (D_HID * D_OUT) / 2) {
        float2 v = ((const float2*)W2)[i];
        ((__half2*)g_w2h)[i] = __floats2half2_rn(v.x, v.y);
    }
    __syncthreads();
    if (t < NG && hist[t]) atomicAdd(&g_gcnt[t], hist[t]);
}

// ---------------- CSR scan pass 1 + dinv ----------------
__global__ void k_scan1(int n) {
    __shared__ int s[256];
    int t = threadIdx.x, b = blockIdx.x;
    int i = b * 256 + t;
    int v = (i < n) ? g_cnt[i] : 0;
    if (i < n) g_dinv[i] = rsqrtf((float)(v + 1));   // self-loop folded
    s[t] = v;
    __syncthreads();
    #pragma unroll
    for (int off = 1; off < 256; off <<= 1) {
        int add = (t >= off) ? s[t - off] : 0;
        __syncthreads();
        s[t] += add;
        __syncthreads();
    }
    if (i < n) g_rowptr[i] = s[t] - v;       // block-local exclusive
    if (t == 255) g_bsum[b] = s[255];
}

// finalize: every block redundantly scans the 196 block sums in smem,
// applies its offset. (No fillptr needed — fill is rank-based.)
__global__ void k_scan3(int n, int e, int nb) {
    __shared__ int s[256];
    int t = threadIdx.x, b = blockIdx.x;
    int v = (t < nb) ? g_bsum[t] : 0;
    s[t] = v;
    __syncthreads();
    #pragma unroll
    for (int off = 1; off < 256; off <<= 1) {
        int add = (t >= off) ? s[t - off] : 0;
        __syncthreads();
        s[t] += add;
        __syncthreads();
    }
    int boff = (b == 0) ? 0 : s[b - 1];

    int i = b * 256 + t;
    if (i < n) g_rowptr[i] += boff;
    if (i == 0) g_rowptr[n] = e;
}

// fill CSR cols — ATOMIC-FREE: pos = rowptr[dst] + rank[edge].
// 4 edges/thread; re-zeros g_cnt for the next replay.
__global__ void k_fill(const int* __restrict__ ei, int e4, int n) {
    int i = blockIdx.x * blockDim.x + threadIdx.x;
    if (i < e4) {
        int4 s = ((const int4*)ei)[i];
        int4 d = ((const int4*)ei)[e4 + i];
        int4 r = ((const int4*)g_rank)[i];
        int p0 = g_rowptr[d.x] + r.x;     // 4 independent L2 loads (good MLP)
        int p1 = g_rowptr[d.y] + r.y;
        int p2 = g_rowptr[d.z] + r.z;
        int p3 = g_rowptr[d.w] + r.w;
        g_col[p0] = s.x;
        g_col[p1] = s.y;
        g_col[p2] = s.z;
        g_col[p3] = s.w;
    }
    if (i < n) g_cnt[i] = 0;
}

// ---------------- tensor-core GEMM ----------------
// out[r,:] = half( (X[r,:128] @ W[:128,:N]) * dinv[r] )
// LAYER=1: X = fp32 arg, W = fp32 arg (converted in-kernel) -> g_hs1.
// LAYER=2: X = g_out1 (fp16), W = g_w2h -> g_hs2.
__device__ __forceinline__ uint32_t smem_u32(const void* p) {
    return (uint32_t)__cvta_generic_to_shared(p);
}
__device__ __forceinline__ void ldsm_x4(uint32_t& a0, uint32_t& a1,
                                        uint32_t& a2, uint32_t& a3, uint32_t addr) {
    asm volatile("ldmatrix.sync.aligned.m8n8.x4.shared.b16 {%0,%1,%2,%3},[%4];"
                 : "=r"(a0), "=r"(a1), "=r"(a2), "=r"(a3) : "r"(addr));
}
__device__ __forceinline__ void ldsm_x2t(uint32_t& b0, uint32_t& b1, uint32_t addr) {
    asm volatile("ldmatrix.sync.aligned.m8n8.x2.trans.shared.b16 {%0,%1},[%2];"
                 : "=r"(b0), "=r"(b1) : "r"(addr));
}
__device__ __forceinline__ void mma16816(float* c, uint32_t a0, uint32_t a1,
                                         uint32_t a2, uint32_t a3,
                                         uint32_t b0, uint32_t b1) {
    asm volatile(
        "mma.sync.aligned.m16n8k16.row.col.f32.f16.f16.f32 "
        "{%0,%1,%2,%3}, {%4,%5,%6,%7}, {%8,%9}, {%0,%1,%2,%3};"
        : "+f"(c[0]), "+f"(c[1]), "+f"(c[2]), "+f"(c[3])
        : "r"(a0), "r"(a1), "r"(a2), "r"(a3), "r"(b0), "r"(b1));
}
__device__ __forceinline__ uint4 f8_to_h8(float4 f0, float4 f1) {
    __half2 p0 = __floats2half2_rn(f0.x, f0.y), p1 = __floats2half2_rn(f0.z, f0.w);
    __half2 p2 = __floats2half2_rn(f1.x, f1.y), p3 = __floats2half2_rn(f1.z, f1.w);
    uint4 v;
    v.x = *(uint32_t*)&p0; v.y = *(uint32_t*)&p1;
    v.z = *(uint32_t*)&p2; v.w = *(uint32_t*)&p3;
    return v;
}

template <int N, int LAYER>
__global__ __launch_bounds__(256) void k_mma(const float* __restrict__ Xf,
                                             const float* __restrict__ Wf, int M) {
    constexpr int K  = 128;
    constexpr int UW = N / 8;            // 16B units per W row
    constexpr int NJ = N / 32;           // 8-col n-tiles per warp
    __shared__ __align__(16) __half Xs[64 * K];
    __shared__ __align__(16) __half Ws[K * N];

    int tid = threadIdx.x;
    int row0 = blockIdx.x * 64;

    // ---- load W (swizzled) ----
    if (LAYER == 1) {
        #pragma unroll
        for (int t = tid; t < K * UW; t += 256) {
            int r = t / UW, u = t % UW;
            const float4* src = (const float4*)(Wf + r * N + u * 8);
            uint4 v = f8_to_h8(src[0], src[1]);
            *(uint4*)(Ws + ((r * UW) + (u ^ (r & 7))) * 8) = v;
        }
    } else {
        const uint4* Wh = (const uint4*)g_w2h;
        #pragma unroll
        for (int t = tid; t < K * UW; t += 256) {
            int r = t / UW, u = t % UW;
            *(uint4*)(Ws + ((r * UW) + (u ^ (r & 7))) * 8) = Wh[r * UW + u];
        }
    }
    // ---- load X tile (swizzled) ----
    if (LAYER == 1) {
        #pragma unroll
        for (int t = tid; t < 64 * 16; t += 256) {
            int r = t / 16, u = t % 16;
            int gr = min(row0 + r, M - 1);
            const float4* src = (const float4*)(Xf + (size_t)gr * K + u * 8);
            uint4 v = f8_to_h8(src[0], src[1]);
            *(uint4*)(Xs + ((r * 16) + (u ^ (r & 7))) * 8) = v;
        }
    } else {
        const uint4* Xh = (const uint4*)g_out1;
        #pragma unroll
        for (int t = tid; t < 64 * 16; t += 256) {
            int r = t / 16, u = t % 16;
            int gr = min(row0 + r, M - 1);
            uint4 v = Xh[(size_t)gr * 16 + u];
            *(uint4*)(Xs + ((r * 16) + (u ^ (r & 7))) * 8) = v;
        }
    }
    __syncthreads();

    int lane = tid & 31, wid = tid >> 5;
    int wm = wid >> 2;                   // 0..1  (32-row group)
    int wn = wid & 3;                    // 0..3  (N/4-col group)

    float acc[2][NJ][4];
    #pragma unroll
    for (int mt = 0; mt < 2; mt++)
        #pragma unroll
        for (int j = 0; j < NJ; j++)
            #pragma unroll
            for (int q = 0; q < 4; q++) acc[mt][j][q] = 0.0f;

    int asel = lane >> 4;
    int brr = lane & 15;

    #pragma unroll
    for (int ks = 0; ks < 8; ks++) {
        uint32_t a[2][4];
        int uA = ks * 2 + asel;
        #pragma unroll
        for (int mt = 0; mt < 2; mt++) {
            int ar = wm * 32 + mt * 16 + (lane & 15);
            ldsm_x4(a[mt][0], a[mt][1], a[mt][2], a[mt][3],
                    smem_u32(&Xs[((ar * 16) + (uA ^ (ar & 7))) * 8]));
        }
        int rB = ks * 16 + brr;
        #pragma unroll
        for (int j = 0; j < NJ; j++) {
            int uB = wn * (N / 32) + j;
            uint32_t b0, b1;
            ldsm_x2t(b0, b1, smem_u32(&Ws[((rB * UW) + (uB ^ (rB & 7))) * 8]));
            #pragma unroll
            for (int mt = 0; mt < 2; mt++)
                mma16816(acc[mt][j], a[mt][0], a[mt][1], a[mt][2], a[mt][3], b0, b1);
        }
    }

    // ---- epilogue: *dinv, fp16 store ----
    __half2* out = (LAYER == 1) ? (__half2*)g_hs1 : (__half2*)g_hs2;
    #pragma unroll
    for (int mt = 0; mt < 2; mt++) {
        int gr0 = row0 + wm * 32 + mt * 16 + (lane >> 2);
        int gr1 = gr0 + 8;
        float dv0 = (gr0 < M) ? g_dinv[gr0] : 0.0f;
        float dv1 = (gr1 < M) ? g_dinv[gr1] : 0.0f;
        #pragma unroll
        for (int j = 0; j < NJ; j++) {
            int c2 = wn * (N / 8) + j * 4 + (lane & 3);
            if (gr0 < M)
                out[(size_t)gr0 * (N / 2) + c2] =
                    __floats2half2_rn(acc[mt][j][0] * dv0, acc[mt][j][1] * dv0);
            if (gr1 < M)
                out[(size_t)gr1 * (N / 2) + c2] =
                    __floats2half2_rn(acc[mt][j][2] * dv1, acc[mt][j][3] * dv1);
        }
    }
}

__device__ __forceinline__ void acc_u2(float2& a0, float2& a1, uint2 v) {
    float2 f0 = __half22float2(*(__half2*)&v.x);
    float2 f1 = __half22float2(*(__half2*)&v.y);
    a0.x += f0.x; a0.y += f0.y;
    a1.x += f1.x; a1.y += f1.y;
}

// ---------------- aggregation layer 1 (DIM=128, fp16 in/out) ----------
__global__ __launch_bounds__(256) void k_agg1(const float* __restrict__ bias, int n) {
    const uint2* hs = (const uint2*)g_hs1;   // row = 32 uint2
    int warp = (blockIdx.x * blockDim.x + threadIdx.x) >> 5;
    int lane = threadIdx.x & 31;
    if (warp >= n) return;
    int node = warp;

    float2 a0 = {0.f, 0.f}, a1 = {0.f, 0.f};
    acc_u2(a0, a1, hs[(size_t)node * 32 + lane]);   // self

    int e = g_rowptr[node];
    int t = g_rowptr[node + 1];
    for (; e + 4 <= t; e += 4) {
        int c0 = g_col[e], c1 = g_col[e + 1], c2 = g_col[e + 2], c3 = g_col[e + 3];
        uint2 v0 = hs[(size_t)c0 * 32 + lane];
        uint2 v1 = hs[(size_t)c1 * 32 + lane];
        uint2 v2 = hs[(size_t)c2 * 32 + lane];
        uint2 v3 = hs[(size_t)c3 * 32 + lane];
        acc_u2(a0, a1, v0); acc_u2(a0, a1, v1);
        acc_u2(a0, a1, v2); acc_u2(a0, a1, v3);
    }
    for (; e < t; e++)
        acc_u2(a0, a1, hs[(size_t)g_col[e] * 32 + lane]);

    float dv = g_dinv[node];
    float4 bb = ((const float4*)bias)[lane];   // cols 4l..4l+3
    __half2 o0 = __floats2half2_rn(fmaxf(fmaf(a0.x, dv, bb.x), 0.0f),
                                   fmaxf(fmaf(a0.y, dv, bb.y), 0.0f));
    __half2 o1 = __floats2half2_rn(fmaxf(fmaf(a1.x, dv, bb.z), 0.0f),
                                   fmaxf(fmaf(a1.y, dv, bb.w), 0.0f));
    uint2 st;
    st.x = *(uint32_t*)&o0; st.y = *(uint32_t*)&o1;
    ((uint2*)g_out1)[(size_t)node * 32 + lane] = st;
}

__device__ __forceinline__ void acc_h2(float2& a, __half2 h) {
    float2 f = __half22float2(h);
    a.x += f.x; a.y += f.y;
}

// ---------------- aggregation layer 2 (DIM=64, fp16 in, pool) ----------
__global__ __launch_bounds__(256) void k_agg2(const float* __restrict__ bias,
                                              const int* __restrict__ batch, int n) {
    const __half2* hs = (const __half2*)g_hs2;   // row = 32 half2
    int warp = (blockIdx.x * blockDim.x + threadIdx.x) >> 5;
    int lane = threadIdx.x & 31;
    if (warp >= n) return;
    int node = warp;

    float2 a0 = __half22float2(hs[(size_t)node * 32 + lane]);

    int e = g_rowptr[node];
    int t = g_rowptr[node + 1];
    for (; e + 4 <= t; e += 4) {
        int c0 = g_col[e], c1 = g_col[e + 1], c2 = g_col[e + 2], c3 = g_col[e + 3];
        __half2 v0 = hs[(size_t)c0 * 32 + lane];
        __half2 v1 = hs[(size_t)c1 * 32 + lane];
        __half2 v2 = hs[(size_t)c2 * 32 + lane];
        __half2 v3 = hs[(size_t)c3 * 32 + lane];
        acc_h2(a0, v0); acc_h2(a0, v1); acc_h2(a0, v2); acc_h2(a0, v3);
    }
    for (; e < t; e++)
        acc_h2(a0, hs[(size_t)g_col[e] * 32 + lane]);

    float dv = g_dinv[node];
    float2 bb = ((const float2*)bias)[lane];
    int gidx = batch[node];
    atomicAdd(&g_gsum[gidx * D_OUT + 2 * lane + 0], fmaf(a0.x, dv, bb.x));
    atomicAdd(&g_gsum[gidx * D_OUT + 2 * lane + 1], fmaf(a0.y, dv, bb.y));
}

// ---------------- final divide + re-zero pool state ----------------
__global__ void k_final(float* __restrict__ out) {
    int i = blockIdx.x * blockDim.x + threadIdx.x;
    if (i < NG * D_OUT) {
        int g = i / D_OUT;
        float c = (float)max(g_gcnt[g], 1);
        out[i] = g_gsum[i] / c;
        g_gsum[i] = 0.0f;
    }
    if (i < NG) g_gcnt[i] = 0;
}

// ---------------- launch (graph-capturable; serial, no host objects) ----
extern "C" void kernel_launch(void* const* d_in, const int* in_sizes, int n_in,
                              void* d_out, int out_size) {
    const float* x = nullptr; const int* ei = nullptr; const int* batch = nullptr;
    const float* W1 = nullptr; const float* b1 = nullptr;
    const float* W2 = nullptr; const float* b2 = nullptr;
    for (int i = 0; i < n_in; i++) {
        switch (in_sizes[i]) {
            case NN * D_IN:      x     = (const float*)d_in[i]; break;
            case 2 * NE:         ei    = (const int*)d_in[i];   break;
            case NN:             batch = (const int*)d_in[i];   break;
            case D_IN * D_HID:   W1    = (const float*)d_in[i]; break;
            case D_HID * D_OUT:  W2    = (const float*)d_in[i]; break;
            case D_HID:          b1    = (const float*)d_in[i]; break;
            case D_OUT:          b2    = (const float*)d_in[i]; break;
        }
    }
    float* out = (float*)d_out;

    const int n = NN, e = NE;
    const int e4 = NE / 4;                // 150000
    const int nb256n = (n + 255) / 256;   // 196
    const int nb256e4 = (e4 + 255) / 256; // 586
    int gb = (n + 63) / 64;               // 782

    k_deg<<<nb256e4, 256>>>(ei, batch, W2, e4, n);
    k_scan1<<<nb256n, 256>>>(n);
    k_scan3<<<nb256n, 256>>>(n, e, nb256n);
    k_fill<<<nb256e4, 256>>>(ei, e4, n);

    k_mma<128, 1><<<gb, 256>>>(x, W1, n);
    k_agg1<<<(n + 7) / 8, 256>>>(b1, n);
    k_mma<64, 2><<<gb, 256>>>(nullptr, nullptr, n);
    k_agg2<<<(n + 7) / 8, 256>>>(b2, batch, n);
    k_final<<<(NG * D_OUT + 255) / 256, 256>>>(out);
}

// round 17
// speedup vs baseline: 1.0206x; 1.0149x over previous
#include <cuda_runtime.h>
#include <cuda_fp16.h>
#include <cstdint>

// Problem constants (fixed by the reference)
#define NN 50000
#define NE 600000
#define NG 64
#define D_IN 128
#define D_HID 128
#define D_OUT 64

// ---------------- device scratch (no allocs allowed) ----------------
// Invariant: g_cnt, g_gsum, g_gcnt are ZERO at entry of every kernel_launch
// call (BSS-zero initially; re-zeroed at the end of fill / k_final).
__device__ __align__(16) int    g_cnt[NN];        // in-degree (edges only)
__device__ __align__(16) float  g_dinv[NN];
__device__ __align__(16) int    g_rowptr[NN + 1];
__device__ __align__(16) int    g_rank[NE];       // per-edge insertion rank
__device__ __align__(16) int    g_bsum[256];
__device__ __align__(16) int    g_col[NE];
__device__ __align__(16) __half g_w2h[D_HID * D_OUT];  // fp16 W2
__device__ __align__(16) __half g_hs1[NN * D_HID];   // (x@W1)*dinv[row], fp16
__device__ __align__(16) __half g_out1[NN * D_HID];  // relu(layer1 agg), fp16
__device__ __align__(16) __half g_hs2[NN * D_OUT];   // (out1@W2)*dinv[row], fp16
__device__ __align__(16) float  g_gsum[NG * D_OUT];
__device__ __align__(16) int    g_gcnt[NG];

// ------- degree + per-edge rank + graph histogram + W2 fp16 convert -------
__global__ void k_deg(const int* __restrict__ ei, const int* __restrict__ batch,
                      const float* __restrict__ W2, int e4, int n) {
    __shared__ int hist[NG];
    int t = threadIdx.x;
    if (t < NG) hist[t] = 0;
    __syncthreads();
    int i = blockIdx.x * blockDim.x + t;
    if (i < e4) {                         // 4 dst indices, one 16B load
        int4 d = ((const int4*)ei)[e4 + i];
        int4 r;
        r.x = atomicAdd(&g_cnt[d.x], 1);
        r.y = atomicAdd(&g_cnt[d.y], 1);
        r.z = atomicAdd(&g_cnt[d.z], 1);
        r.w = atomicAdd(&g_cnt[d.w], 1);
        ((int4*)g_rank)[i] = r;           // streaming 16B store
    }
    if (i < n) atomicAdd(&hist[batch[i]], 1);
    if (i < (D_HID * D_OUT) / 2) {
        float2 v = ((const float2*)W2)[i];
        ((__half2*)g_w2h)[i] = __floats2half2_rn(v.x, v.y);
    }
    __syncthreads();
    if (t < NG && hist[t]) atomicAdd(&g_gcnt[t], hist[t]);
}

// ---------------- CSR scan pass 1 + dinv ----------------
__global__ void k_scan1(int n) {
    __shared__ int s[256];
    int t = threadIdx.x, b = blockIdx.x;
    int i = b * 256 + t;
    int v = (i < n) ? g_cnt[i] : 0;
    if (i < n) g_dinv[i] = rsqrtf((float)(v + 1));   // self-loop folded
    s[t] = v;
    __syncthreads();
    #pragma unroll
    for (int off = 1; off < 256; off <<= 1) {
        int add = (t >= off) ? s[t - off] : 0;
        __syncthreads();
        s[t] += add;
        __syncthreads();
    }
    if (i < n) g_rowptr[i] = s[t] - v;       // block-local exclusive
    if (t == 255) g_bsum[b] = s[255];
}

// finalize: every block redundantly scans the 196 block sums in smem.
__global__ void k_scan3(int n, int e, int nb) {
    __shared__ int s[256];
    int t = threadIdx.x, b = blockIdx.x;
    int v = (t < nb) ? g_bsum[t] : 0;
    s[t] = v;
    __syncthreads();
    #pragma unroll
    for (int off = 1; off < 256; off <<= 1) {
        int add = (t >= off) ? s[t - off] : 0;
        __syncthreads();
        s[t] += add;
        __syncthreads();
    }
    int boff = (b == 0) ? 0 : s[b - 1];

    int i = b * 256 + t;
    if (i < n) g_rowptr[i] += boff;
    if (i == 0) g_rowptr[n] = e;
}

// ---------------- tensor-core GEMM helpers ----------------
__device__ __forceinline__ uint32_t smem_u32(const void* p) {
    return (uint32_t)__cvta_generic_to_shared(p);
}
__device__ __forceinline__ void ldsm_x4(uint32_t& a0, uint32_t& a1,
                                        uint32_t& a2, uint32_t& a3, uint32_t addr) {
    asm volatile("ldmatrix.sync.aligned.m8n8.x4.shared.b16 {%0,%1,%2,%3},[%4];"
                 : "=r"(a0), "=r"(a1), "=r"(a2), "=r"(a3) : "r"(addr));
}
__device__ __forceinline__ void ldsm_x2t(uint32_t& b0, uint32_t& b1, uint32_t addr) {
    asm volatile("ldmatrix.sync.aligned.m8n8.x2.trans.shared.b16 {%0,%1},[%2];"
                 : "=r"(b0), "=r"(b1) : "r"(addr));
}
__device__ __forceinline__ void mma16816(float* c, uint32_t a0, uint32_t a1,
                                         uint32_t a2, uint32_t a3,
                                         uint32_t b0, uint32_t b1) {
    asm volatile(
        "mma.sync.aligned.m16n8k16.row.col.f32.f16.f16.f32 "
        "{%0,%1,%2,%3}, {%4,%5,%6,%7}, {%8,%9}, {%0,%1,%2,%3};"
        : "+f"(c[0]), "+f"(c[1]), "+f"(c[2]), "+f"(c[3])
        : "r"(a0), "r"(a1), "r"(a2), "r"(a3), "r"(b0), "r"(b1));
}
__device__ __forceinline__ uint4 f8_to_h8(float4 f0, float4 f1) {
    __half2 p0 = __floats2half2_rn(f0.x, f0.y), p1 = __floats2half2_rn(f0.z, f0.w);
    __half2 p2 = __floats2half2_rn(f1.x, f1.y), p3 = __floats2half2_rn(f1.z, f1.w);
    uint4 v;
    v.x = *(uint32_t*)&p0; v.y = *(uint32_t*)&p1;
    v.z = *(uint32_t*)&p2; v.w = *(uint32_t*)&p3;
    return v;
}

// mma body as device function: out[r,:] = half((X[r,:]@W)*dinv[r]).
// LAYER=1: X fp32, W fp32 (in-body convert) -> g_hs1.
// LAYER=2: X = g_out1 fp16, W = g_w2h -> g_hs2.
template <int N, int LAYER>
__device__ __forceinline__ void mma_body(const float* __restrict__ Xf,
                                         const float* __restrict__ Wf,
                                         int M, int row0, int tid) {
    constexpr int K  = 128;
    constexpr int UW = N / 8;            // 16B units per W row
    constexpr int NJ = N / 32;           // 8-col n-tiles per warp
    __shared__ __align__(16) __half Xs[64 * K];
    __shared__ __align__(16) __half Ws[K * N];

    // ---- load W (swizzled) ----
    if (LAYER == 1) {
        #pragma unroll
        for (int t = tid; t < K * UW; t += 256) {
            int r = t / UW, u = t % UW;
            const float4* src = (const float4*)(Wf + r * N + u * 8);
            uint4 v = f8_to_h8(src[0], src[1]);
            *(uint4*)(Ws + ((r * UW) + (u ^ (r & 7))) * 8) = v;
        }
    } else {
        const uint4* Wh = (const uint4*)g_w2h;
        #pragma unroll
        for (int t = tid; t < K * UW; t += 256) {
            int r = t / UW, u = t % UW;
            *(uint4*)(Ws + ((r * UW) + (u ^ (r & 7))) * 8) = Wh[r * UW + u];
        }
    }
    // ---- load X tile (swizzled) ----
    if (LAYER == 1) {
        #pragma unroll
        for (int t = tid; t < 64 * 16; t += 256) {
            int r = t / 16, u = t % 16;
            int gr = min(row0 + r, M - 1);
            const float4* src = (const float4*)(Xf + (size_t)gr * K + u * 8);
            uint4 v = f8_to_h8(src[0], src[1]);
            *(uint4*)(Xs + ((r * 16) + (u ^ (r & 7))) * 8) = v;
        }
    } else {
        const uint4* Xh = (const uint4*)g_out1;
        #pragma unroll
        for (int t = tid; t < 64 * 16; t += 256) {
            int r = t / 16, u = t % 16;
            int gr = min(row0 + r, M - 1);
            uint4 v = Xh[(size_t)gr * 16 + u];
            *(uint4*)(Xs + ((r * 16) + (u ^ (r & 7))) * 8) = v;
        }
    }
    __syncthreads();

    int lane = tid & 31, wid = tid >> 5;
    int wm = wid >> 2;                   // 0..1  (32-row group)
    int wn = wid & 3;                    // 0..3  (N/4-col group)

    float acc[2][NJ][4];
    #pragma unroll
    for (int mt = 0; mt < 2; mt++)
        #pragma unroll
        for (int j = 0; j < NJ; j++)
            #pragma unroll
            for (int q = 0; q < 4; q++) acc[mt][j][q] = 0.0f;

    int asel = lane >> 4;
    int brr = lane & 15;

    #pragma unroll
    for (int ks = 0; ks < 8; ks++) {
        uint32_t a[2][4];
        int uA = ks * 2 + asel;
        #pragma unroll
        for (int mt = 0; mt < 2; mt++) {
            int ar = wm * 32 + mt * 16 + (lane & 15);
            ldsm_x4(a[mt][0], a[mt][1], a[mt][2], a[mt][3],
                    smem_u32(&Xs[((ar * 16) + (uA ^ (ar & 7))) * 8]));
        }
        int rB = ks * 16 + brr;
        #pragma unroll
        for (int j = 0; j < NJ; j++) {
            int uB = wn * (N / 32) + j;
            uint32_t b0, b1;
            ldsm_x2t(b0, b1, smem_u32(&Ws[((rB * UW) + (uB ^ (rB & 7))) * 8]));
            #pragma unroll
            for (int mt = 0; mt < 2; mt++)
                mma16816(acc[mt][j], a[mt][0], a[mt][1], a[mt][2], a[mt][3], b0, b1);
        }
    }

    // ---- epilogue: *dinv, fp16 store ----
    __half2* out = (LAYER == 1) ? (__half2*)g_hs1 : (__half2*)g_hs2;
    #pragma unroll
    for (int mt = 0; mt < 2; mt++) {
        int gr0 = row0 + wm * 32 + mt * 16 + (lane >> 2);
        int gr1 = gr0 + 8;
        float dv0 = (gr0 < M) ? g_dinv[gr0] : 0.0f;
        float dv1 = (gr1 < M) ? g_dinv[gr1] : 0.0f;
        #pragma unroll
        for (int j = 0; j < NJ; j++) {
            int c2 = wn * (N / 8) + j * 4 + (lane & 3);
            if (gr0 < M)
                out[(size_t)gr0 * (N / 2) + c2] =
                    __floats2half2_rn(acc[mt][j][0] * dv0, acc[mt][j][1] * dv0);
            if (gr1 < M)
                out[(size_t)gr1 * (N / 2) + c2] =
                    __floats2half2_rn(acc[mt][j][2] * dv1, acc[mt][j][3] * dv1);
        }
    }
}

// ---- fused launch: CSR fill (atomic-free) + mma1, role by block parity ----
// fill needs rowptr (ready after scan3); mma1 needs dinv (ready after scan1);
// their outputs (g_col, g_hs1) are consumed only by agg1 — no mutual dep.
// Interleave roles so each occupancy wave mixes latency-bound fill blocks
// with tensor-bound mma blocks.
#define FB 586                      // fill blocks (e4 = 150000 / 256)
__global__ __launch_bounds__(256) void k_fillmma(const int* __restrict__ ei,
                                                 const float* __restrict__ Xf,
                                                 const float* __restrict__ Wf,
                                                 int e4, int n, int M) {
    int bid = blockIdx.x;
    int tid = threadIdx.x;
    bool is_fill;
    int role_id;
    if (bid < 2 * FB) {             // interleaved region
        is_fill = (bid & 1) == 0;
        role_id = bid >> 1;
    } else {                        // tail: all mma
        is_fill = false;
        role_id = FB + (bid - 2 * FB);
    }

    if (is_fill) {
        int i = role_id * 256 + tid;
        if (i < e4) {
            int4 s = ((const int4*)ei)[i];
            int4 d = ((const int4*)ei)[e4 + i];
            int4 r = ((const int4*)g_rank)[i];
            int p0 = g_rowptr[d.x] + r.x;
            int p1 = g_rowptr[d.y] + r.y;
            int p2 = g_rowptr[d.z] + r.z;
            int p3 = g_rowptr[d.w] + r.w;
            g_col[p0] = s.x;
            g_col[p1] = s.y;
            g_col[p2] = s.z;
            g_col[p3] = s.w;
        }
        if (i < n) g_cnt[i] = 0;    // re-zero for next replay
    } else {
        mma_body<128, 1>(Xf, Wf, M, role_id * 64, tid);
    }
}

// layer-2 GEMM (standalone)
__global__ __launch_bounds__(256) void k_mma2(int M) {
    mma_body<64, 2>(nullptr, nullptr, M, blockIdx.x * 64, threadIdx.x);
}

__device__ __forceinline__ void acc_u2(float2& a0, float2& a1, uint2 v) {
    float2 f0 = __half22float2(*(__half2*)&v.x);
    float2 f1 = __half22float2(*(__half2*)&v.y);
    a0.x += f0.x; a0.y += f0.y;
    a1.x += f1.x; a1.y += f1.y;
}

// ---------------- aggregation layer 1 (DIM=128, fp16 in/out) ----------
__global__ __launch_bounds__(256) void k_agg1(const float* __restrict__ bias, int n) {
    const uint2* hs = (const uint2*)g_hs1;   // row = 32 uint2
    int warp = (blockIdx.x * blockDim.x + threadIdx.x) >> 5;
    int lane = threadIdx.x & 31;
    if (warp >= n) return;
    int node = warp;

    float2 a0 = {0.f, 0.f}, a1 = {0.f, 0.f};
    acc_u2(a0, a1, hs[(size_t)node * 32 + lane]);   // self

    int e = g_rowptr[node];
    int t = g_rowptr[node + 1];
    for (; e + 4 <= t; e += 4) {
        int c0 = g_col[e], c1 = g_col[e + 1], c2 = g_col[e + 2], c3 = g_col[e + 3];
        uint2 v0 = hs[(size_t)c0 * 32 + lane];
        uint2 v1 = hs[(size_t)c1 * 32 + lane];
        uint2 v2 = hs[(size_t)c2 * 32 + lane];
        uint2 v3 = hs[(size_t)c3 * 32 + lane];
        acc_u2(a0, a1, v0); acc_u2(a0, a1, v1);
        acc_u2(a0, a1, v2); acc_u2(a0, a1, v3);
    }
    for (; e < t; e++)
        acc_u2(a0, a1, hs[(size_t)g_col[e] * 32 + lane]);

    float dv = g_dinv[node];
    float4 bb = ((const float4*)bias)[lane];   // cols 4l..4l+3
    __half2 o0 = __floats2half2_rn(fmaxf(fmaf(a0.x, dv, bb.x), 0.0f),
                                   fmaxf(fmaf(a0.y, dv, bb.y), 0.0f));
    __half2 o1 = __floats2half2_rn(fmaxf(fmaf(a1.x, dv, bb.z), 0.0f),
                                   fmaxf(fmaf(a1.y, dv, bb.w), 0.0f));
    uint2 st;
    st.x = *(uint32_t*)&o0; st.y = *(uint32_t*)&o1;
    ((uint2*)g_out1)[(size_t)node * 32 + lane] = st;
}

__device__ __forceinline__ void acc_h2(float2& a, __half2 h) {
    float2 f = __half22float2(h);
    a.x += f.x; a.y += f.y;
}

// ---------------- aggregation layer 2 (DIM=64, fp16 in, pool) ----------
__global__ __launch_bounds__(256) void k_agg2(const float* __restrict__ bias,
                                              const int* __restrict__ batch, int n) {
    const __half2* hs = (const __half2*)g_hs2;   // row = 32 half2
    int warp = (blockIdx.x * blockDim.x + threadIdx.x) >> 5;
    int lane = threadIdx.x & 31;
    if (warp >= n) return;
    int node = warp;

    float2 a0 = __half22float2(hs[(size_t)node * 32 + lane]);

    int e = g_rowptr[node];
    int t = g_rowptr[node + 1];
    for (; e + 4 <= t; e += 4) {
        int c0 = g_col[e], c1 = g_col[e + 1], c2 = g_col[e + 2], c3 = g_col[e + 3];
        __half2 v0 = hs[(size_t)c0 * 32 + lane];
        __half2 v1 = hs[(size_t)c1 * 32 + lane];
        __half2 v2 = hs[(size_t)c2 * 32 + lane];
        __half2 v3 = hs[(size_t)c3 * 32 + lane];
        acc_h2(a0, v0); acc_h2(a0, v1); acc_h2(a0, v2); acc_h2(a0, v3);
    }
    for (; e < t; e++)
        acc_h2(a0, hs[(size_t)g_col[e] * 32 + lane]);

    float dv = g_dinv[node];
    float2 bb = ((const float2*)bias)[lane];
    int gidx = batch[node];
    atomicAdd(&g_gsum[gidx * D_OUT + 2 * lane + 0], fmaf(a0.x, dv, bb.x));
    atomicAdd(&g_gsum[gidx * D_OUT + 2 * lane + 1], fmaf(a0.y, dv, bb.y));
}

// ---------------- final divide + re-zero pool state ----------------
__global__ void k_final(float* __restrict__ out) {
    int i = blockIdx.x * blockDim.x + threadIdx.x;
    if (i < NG * D_OUT) {
        int g = i / D_OUT;
        float c = (float)max(g_gcnt[g], 1);
        out[i] = g_gsum[i] / c;
        g_gsum[i] = 0.0f;
    }
    if (i < NG) g_gcnt[i] = 0;
}

// ---------------- launch (graph-capturable; serial, no host objects) ----
extern "C" void kernel_launch(void* const* d_in, const int* in_sizes, int n_in,
                              void* d_out, int out_size) {
    const float* x = nullptr; const int* ei = nullptr; const int* batch = nullptr;
    const float* W1 = nullptr; const float* b1 = nullptr;
    const float* W2 = nullptr; const float* b2 = nullptr;
    for (int i = 0; i < n_in; i++) {
        switch (in_sizes[i]) {
            case NN * D_IN:      x     = (const float*)d_in[i]; break;
            case 2 * NE:         ei    = (const int*)d_in[i];   break;
            case NN:             batch = (const int*)d_in[i];   break;
            case D_IN * D_HID:   W1    = (const float*)d_in[i]; break;
            case D_HID * D_OUT:  W2    = (const float*)d_in[i]; break;
            case D_HID:          b1    = (const float*)d_in[i]; break;
            case D_OUT:          b2    = (const float*)d_in[i]; break;
        }
    }
    float* out = (float*)d_out;

    const int n = NN, e = NE;
    const int e4 = NE / 4;                // 150000
    const int nb256n = (n + 255) / 256;   // 196
    const int nb256e4 = (e4 + 255) / 256; // 586  (== FB)
    int gb = (n + 63) / 64;               // 782

    k_deg<<<nb256e4, 256>>>(ei, batch, W2, e4, n);
    k_scan1<<<nb256n, 256>>>(n);
    k_scan3<<<nb256n, 256>>>(n, e, nb256n);

    // fused: CSR fill + layer-1 GEMM (independent work, one launch)
    k_fillmma<<<FB + gb, 256>>>(ei, x, W1, e4, n, n);

    k_agg1<<<(n + 7) / 8, 256>>>(b1, n);
    k_mma2<<<gb, 256>>>(n);
    k_agg2<<<(n + 7) / 8, 256>>>(b2, batch, n);
    k_final<<<(NG * D_OUT + 255) / 256, 256>>>(out);
}